// round 14
// baseline (speedup 1.0000x reference)
#include <cuda_runtime.h>

// SpectralConv2d via truncated-mode DFTs, fp32 SIMT, register-tiled.
// R14: kAB part1 gets a second fold (w <-> 128-w, k-parity split) halving its
// FLOPs; thread owns rows (rg, rg+128) so the h-fold happens in registers.

#define BB 16
#define CC 64
#define HH 256
#define WW 256
#define M1 20
#define M2 20
#define QQ 40   // q<20 -> ky=236+q (w2, m=q); q>=20 -> ky=q-20 (w1, m=q-20); freq f = q-20

__device__ float2 g_Zq[BB*CC*QQ*M2];   // after H-DFT   [b,c,q,k2]
__device__ float2 g_Zo[BB*CC*QQ*M2];   // after mixing  [b,o,q,k2]

// ---------------------------------------------------------------------------
// Stage AB (fused): block = one (b,c) slice (grid 1024), 256 threads.
// part 1 (W-DFT, double-folded):
//   u[w]=x[w]+x[256-w], v[w]=x[w]-x[256-w]  (w=1..127)
//   Re(k) = x0 + (-1)^k x128 + u64*cos(pi k/2)
//           + sum_{w=1}^{63} (u[w] +- u[128-w]) cos(2pi k w/256)   (+ even k / - odd k)
//   Im(k) = -( v64*sin(pi k/2) + sum_{w=1}^{63} (v[w] -+ v[128-w]) sin(2pi k w/256) )
//   thread -> (rows rg & rg+128, 10 k of one parity); h-fold in registers.
// part 2 (H-DFT): Zq[q,k2] = sum_{h<128} plane(f&1)[h][k2] e^{-2pi i f h/256}.
// ---------------------------------------------------------------------------
#define WCH8 8
__global__ void __launch_bounds__(256, 2) kAB(const float* __restrict__ x) {
    __shared__ float2 tw[256];             // 2KB
    __shared__ float2 sfE[HH][WCH8 + 2];   // 20KB  even-k plane (up, vm)
    __shared__ float2 sfO[HH][WCH8 + 2];   // 20KB  odd-k plane  (um, vp)
    __shared__ float4 sEdge[HH];           // 4KB   (x0, x128, u64, v64)
    __shared__ float4 twa[2][4][10];       // 1.3KB (c@w0, s@w0, c@w1, s@w1) per (parity, wpair, j)
    __shared__ float2 sY[HH][M2];          // 40KB
    int tid = threadIdx.x;
    {
        float s, c;
        sincospif((float)tid * (1.0f / 128.0f), &s, &c);
        tw[tid] = make_float2(c, s);
    }
    int bc = blockIdx.x;
    const float* xb = x + (size_t)bc * HH * WW;
    int rg = tid >> 1;            // 0..127 -> rows rg, rg+128
    int kg = tid & 1;             // k parity: k = 2j + kg

    float ar[2][10], ai[2][10];
    #pragma unroll
    for (int u = 0; u < 2; ++u)
        #pragma unroll
        for (int j = 0; j < 10; ++j) { ar[u][j] = 0.0f; ai[u][j] = 0.0f; }

    const float2 (*sfP)[WCH8 + 2] = kg ? sfO : sfE;

    #pragma unroll 1
    for (int wc = 0; wc < 64; wc += WCH8) {
        __syncthreads();
        // staging: 4-quadrant reads -> double-folded planes
        for (int t = tid; t < HH * WCH8; t += 256) {
            int r = t >> 3, sl = t & 7;
            int w = wc + sl;
            const float* xr = xb + (size_t)r * WW;
            if (w == 0) {
                sEdge[r] = make_float4(xr[0], xr[128], xr[64] + xr[192], xr[64] - xr[192]);
                sfE[r][0] = make_float2(0.f, 0.f);
                sfO[r][0] = make_float2(0.f, 0.f);
            } else {
                float a1 = xr[w], a2 = xr[256 - w], a3 = xr[128 - w], a4 = xr[128 + w];
                float u1 = a1 + a2, v1 = a1 - a2;
                float u2 = a3 + a4, v2 = a3 - a4;
                sfE[r][sl] = make_float2(u1 + u2, v1 - v2);
                sfO[r][sl] = make_float2(u1 - u2, v1 + v2);
            }
        }
        // packed twiddles for this chunk
        if (tid < 80) {
            int p = tid >= 40;
            int t2 = tid - p * 40;
            int wp = t2 / 10, j = t2 - wp * 10;
            int k = 2 * j + p;
            int w0 = wc + 2 * wp;
            float2 c0 = tw[(k * w0) & 255];
            float2 c1 = tw[(k * (w0 + 1)) & 255];
            twa[p][wp][j] = make_float4(c0.x, c0.y, c1.x, c1.y);
        }
        __syncthreads();

        #pragma unroll
        for (int wp = 0; wp < 4; ++wp) {
            float4 A = *(const float4*)&sfP[rg][2 * wp];
            float4 B = *(const float4*)&sfP[rg + 128][2 * wp];
            #pragma unroll
            for (int j = 0; j < 10; ++j) {
                float4 t = twa[kg][wp][j];
                ar[0][j] = fmaf(A.x, t.x, fmaf(A.z, t.z, ar[0][j]));
                ai[0][j] = fmaf(A.y, t.y, fmaf(A.w, t.w, ai[0][j]));
                ar[1][j] = fmaf(B.x, t.x, fmaf(B.z, t.z, ar[1][j]));
                ai[1][j] = fmaf(B.y, t.y, fmaf(B.w, t.w, ai[1][j]));
            }
        }
    }

    // epilogue: edge terms, h-fold in registers, store planes to sY
    {
        float4 e0 = sEdge[rg];
        float4 e1 = sEdge[rg + 128];
        #pragma unroll
        for (int j = 0; j < 10; ++j) {
            int k = 2 * j + kg;
            float sj = (j & 1) ? -1.f : 1.f;
            float re0, im0, re1, im1;
            if (kg == 0) {
                re0 = ar[0][j] + e0.x + e0.y + sj * e0.z;
                im0 = -ai[0][j];
                re1 = ar[1][j] + e1.x + e1.y + sj * e1.z;
                im1 = -ai[1][j];
            } else {
                re0 = ar[0][j] + e0.x - e0.y;
                im0 = -(ai[0][j] + sj * e0.w);
                re1 = ar[1][j] + e1.x - e1.y;
                im1 = -(ai[1][j] + sj * e1.w);
            }
            sY[rg][k]       = make_float2(re0 + re1, im0 + im1);
            sY[rg + 128][k] = make_float2(re0 - re1, im0 - im1);
        }
    }
    __syncthreads();

    // part 2: H-DFT (banked kB loop)
    if (tid < 200) {
        int q = tid / 5;
        int k0 = (tid % 5) * 4;
        int f = q - M1;
        const float2 (*Ys)[M2] = (f & 1) ? (const float2(*)[M2])&sY[128] : (const float2(*)[M2])&sY[0];
        float br[4] = {0, 0, 0, 0}, bi[4] = {0, 0, 0, 0};
        int idx = 0, step = f & 255;
        #pragma unroll 4
        for (int h = 0; h < 128; ++h) {
            float2 cs = tw[idx];
            float4 yab = *(const float4*)&Ys[h][k0];
            float4 ycd = *(const float4*)&Ys[h][k0 + 2];
            float yx[4] = {yab.x, yab.z, ycd.x, ycd.z};
            float yy[4] = {yab.y, yab.w, ycd.y, ycd.w};
            #pragma unroll
            for (int j = 0; j < 4; ++j) {
                br[j] = fmaf(yx[j], cs.x, fmaf(yy[j], cs.y, br[j]));
                bi[j] = fmaf(yy[j], cs.x, fmaf(-yx[j], cs.y, bi[j]));
            }
            idx = (idx + step) & 255;
        }
        float2* zo = g_Zq + (size_t)bc * QQ * M2 + q * M2 + k0;
        #pragma unroll
        for (int j = 0; j < 4; ++j) zo[j] = make_float2(br[j], bi[j]);
    }
}

// ---------------------------------------------------------------------------
// Stage C: Zo[b,o,q,k2] = sum_i Zq[b,i,q,k2] * Wsel[i,o,m,k2]  (complex)
// Block per (q, k2-quad); weights loaded as float4 across 4 k2 (LDG.128);
// thread -> (o, 4 b, 4 k2).
// ---------------------------------------------------------------------------
__global__ void __launch_bounds__(256) kC(const float* __restrict__ w1r, const float* __restrict__ w1i,
                                          const float* __restrict__ w2r, const float* __restrict__ w2i) {
    __shared__ float2 sZ[BB][CC][4];  // 32KB
    int tid = threadIdx.x;
    int q = blockIdx.x / 5, k2b = (blockIdx.x % 5) * 4;

    for (int t = tid; t < BB * CC * 2; t += 256) {
        int pair = t & 1;
        int ci = t >> 1;                 // b*64 + i
        float4 v = *(const float4*)&g_Zq[(size_t)ci * (QQ * M2) + q * M2 + k2b + pair * 2];
        *(float4*)&sZ[ci >> 6][ci & 63][pair * 2] = v;
    }

    const float *wr, *wi;
    int m;
    if (q < M1) { wr = w2r; wi = w2i; m = q; }
    else        { wr = w1r; wi = w1i; m = q - M1; }
    __syncthreads();

    int o = tid & 63;
    int bq = tid >> 6;   // b = bq + 4j
    float ar[4][4], ai[4][4];
    #pragma unroll
    for (int j = 0; j < 4; ++j)
        #pragma unroll
        for (int kk = 0; kk < 4; ++kk) { ar[j][kk] = 0.f; ai[j][kk] = 0.f; }

    size_t wbase = (size_t)o * (M1 * M2) + m * M2 + k2b;
    #pragma unroll 2
    for (int i = 0; i < CC; ++i) {
        float4 wr4 = *(const float4*)&wr[wbase + (size_t)i * (CC * M1 * M2)];
        float4 wi4 = *(const float4*)&wi[wbase + (size_t)i * (CC * M1 * M2)];
        float wra[4] = {wr4.x, wr4.y, wr4.z, wr4.w};
        float wia[4] = {wi4.x, wi4.y, wi4.z, wi4.w};
        #pragma unroll
        for (int j = 0; j < 4; ++j) {
            float4 za = *(const float4*)&sZ[bq + 4 * j][i][0];
            float4 zb = *(const float4*)&sZ[bq + 4 * j][i][2];
            float zx[4] = {za.x, za.z, zb.x, zb.z};
            float zy[4] = {za.y, za.w, zb.y, zb.w};
            #pragma unroll
            for (int kk = 0; kk < 4; ++kk) {
                ar[j][kk] = fmaf(zx[kk], wra[kk], fmaf(-zy[kk], wia[kk], ar[j][kk]));
                ai[j][kk] = fmaf(zx[kk], wia[kk], fmaf( zy[kk], wra[kk], ai[j][kk]));
            }
        }
    }
    #pragma unroll
    for (int j = 0; j < 4; ++j) {
        int b = bq + 4 * j;
        float2* zo = g_Zo + (((size_t)(b * CC + o)) * QQ + q) * M2 + k2b;
        float4 v0 = make_float4(ar[j][0], ai[j][0], ar[j][1], ai[j][1]);
        float4 v1 = make_float4(ar[j][2], ai[j][2], ar[j][3], ai[j][3]);
        *(float4*)&zo[0] = v0;
        *(float4*)&zo[2] = v1;
    }
}

// ---------------------------------------------------------------------------
// Stage D (fused irfft2): block = one bo (grid 1024), 2 CTAs/SM (regs=128).
// phase1: h<->h+128 fold by q-parity. phase2: wp<->128-wp parity fold; one
// twiddle set -> 4 output columns. (Banked R12 form.)
// ---------------------------------------------------------------------------
__global__ void __launch_bounds__(256, 2) kD(float* __restrict__ out) {
    __shared__ float2 tw[256];          // 2KB
    __shared__ float2 sZ[QQ][M2];       // 6.25KB
    __shared__ float  sGx[M2][HH];      // 20KB
    __shared__ float  sGy[M2 - 1][HH];  // 19KB
    __shared__ float  sCw[M2][64];      // 5KB   cos(2pi k wp/256), wp<64
    __shared__ float  sSw[M2][64];      // 5KB   sin(2pi k wp/256), wp<64
    int tid = threadIdx.x;
    {
        float s, c;
        sincospif((float)tid * (1.0f / 128.0f), &s, &c);
        tw[tid] = make_float2(c, s);
    }
    int bo = blockIdx.x;

    const float4* zsrc = (const float4*)(g_Zo + (size_t)bo * QQ * M2);
    float4* zdst = (float4*)&sZ[0][0];
    for (int t = tid; t < QQ * M2 / 2; t += 256) zdst[t] = zsrc[t];
    __syncthreads();

    for (int t = tid; t < M2 * 64; t += 256) {
        int k = t >> 6, wp = t & 63;
        float2 cs = tw[(k * wp) & 255];
        sCw[k][wp] = cs.x;
        sSw[k][wp] = cs.y;
    }

    // ---- phase 1 ----
    {
        int h = tid & 127;
        int k0 = (tid >> 7) * 10;     // 0 or 10
        float ger[10], gei[10], gor[10], goi[10];
        #pragma unroll
        for (int j = 0; j < 10; ++j) { ger[j] = gei[j] = gor[j] = goi[j] = 0.f; }

        int step = (2 * h) & 255;
        int idx = (-20 * h) & 255;
        #pragma unroll 2
        for (int qq = 0; qq < 20; ++qq) {
            float2 cs = tw[idx];
            #pragma unroll
            for (int j = 0; j < 10; ++j) {
                float2 Z = sZ[2 * qq][k0 + j];
                ger[j] = fmaf(Z.x, cs.x, fmaf(-Z.y, cs.y, ger[j]));
                gei[j] = fmaf(Z.x, cs.y, fmaf( Z.y, cs.x, gei[j]));
            }
            idx = (idx + step) & 255;
        }
        idx = (-19 * h) & 255;
        #pragma unroll 2
        for (int qq = 0; qq < 20; ++qq) {
            float2 cs = tw[idx];
            #pragma unroll
            for (int j = 0; j < 10; ++j) {
                float2 Z = sZ[2 * qq + 1][k0 + j];
                gor[j] = fmaf(Z.x, cs.x, fmaf(-Z.y, cs.y, gor[j]));
                goi[j] = fmaf(Z.x, cs.y, fmaf( Z.y, cs.x, goi[j]));
            }
            idx = (idx + step) & 255;
        }
        #pragma unroll
        for (int j = 0; j < 10; ++j) {
            int k = k0 + j;
            sGx[k][h]       = ger[j] + gor[j];
            sGx[k][h + 128] = ger[j] - gor[j];
            if (k > 0) {
                sGy[k - 1][h]       = gei[j] + goi[j];
                sGy[k - 1][h + 128] = gei[j] - goi[j];
            }
        }
    }
    __syncthreads();

    // ---- phase 2: 4h x 2wp tiles, parity-folded over wp ----
    int wpg = tid & 31;       // wp0 = 2*wpg (0..62)
    int hgb = tid >> 5;       // 0..7
    int wp0 = wpg * 2;
    const float sc = 2.0f / 65536.0f;

    #pragma unroll 1
    for (int it = 0; it < 8; ++it) {
        int h0 = it * 32 + hgb * 4;
        float Ce[4][2], Co[4][2], Se[4][2], So[4][2];
        {
            float4 g0 = *(const float4*)&sGx[0][h0];
            float g0a[4] = {g0.x, g0.y, g0.z, g0.w};
            #pragma unroll
            for (int a = 0; a < 4; ++a)
                #pragma unroll
                for (int b = 0; b < 2; ++b) {
                    Ce[a][b] = 0.5f * g0a[a];
                    Co[a][b] = 0.f; Se[a][b] = 0.f; So[a][b] = 0.f;
                }
        }
        #pragma unroll
        for (int k = 1; k < M2; ++k) {
            float4 gx = *(const float4*)&sGx[k][h0];
            float4 gy = *(const float4*)&sGy[k - 1][h0];
            float2 cw = *(const float2*)&sCw[k][wp0];
            float2 sw = *(const float2*)&sSw[k][wp0];
            float gxa[4] = {gx.x, gx.y, gx.z, gx.w};
            float gya[4] = {gy.x, gy.y, gy.z, gy.w};
            float cwb[2] = {cw.x, cw.y};
            float swb[2] = {sw.x, sw.y};
            if (k & 1) {
                #pragma unroll
                for (int a = 0; a < 4; ++a)
                    #pragma unroll
                    for (int b = 0; b < 2; ++b) {
                        Co[a][b] = fmaf(gxa[a], cwb[b], Co[a][b]);
                        So[a][b] = fmaf(gya[a], swb[b], So[a][b]);
                    }
            } else {
                #pragma unroll
                for (int a = 0; a < 4; ++a)
                    #pragma unroll
                    for (int b = 0; b < 2; ++b) {
                        Ce[a][b] = fmaf(gxa[a], cwb[b], Ce[a][b]);
                        Se[a][b] = fmaf(gya[a], swb[b], Se[a][b]);
                    }
            }
        }

        size_t rowbase = ((size_t)bo * HH + h0) * WW;
        #pragma unroll
        for (int a = 0; a < 4; ++a) {
            float* orow = out + rowbase + (size_t)a * WW;
            float o1[2], o2[2], o3[2], o4[2];
            #pragma unroll
            for (int b = 0; b < 2; ++b) {
                float P = Ce[a][b], Q = Co[a][b], R = Se[a][b], T = So[a][b];
                o1[b] = (P + Q - R - T) * sc;   // out[wp]
                o2[b] = (P + Q + R + T) * sc;   // out[256-wp]
                o3[b] = (P - Q + R - T) * sc;   // out[128-wp]
                o4[b] = (P - Q - R + T) * sc;   // out[128+wp]
            }
            *(float2*)&orow[wp0] = make_float2(o1[0], o1[1]);
            if (wpg) {
                orow[256 - wp0]     = o2[0];
                orow[255 - wp0]     = o2[1];
                orow[128 - wp0]     = o3[0];
                orow[127 - wp0]     = o3[1];
                *(float2*)&orow[128 + wp0] = make_float2(o4[0], o4[1]);
            } else {
                orow[255] = o2[1];
                orow[127] = o3[1];
                orow[129] = o4[1];
            }
        }
    }

    // ---- w = 64, 128, 192 columns (per-h epilogue) ----
    {
        int h = tid;
        float g0 = 0.5f * sGx[0][h];
        float accP = g0;
        float accS = 0.f;
        float acc128 = g0;
        #pragma unroll
        for (int k = 1; k < M2; ++k) {
            float gx = sGx[k][h];
            acc128 += (k & 1) ? -gx : gx;
            if (k & 1) {
                float gy = sGy[k - 1][h];
                accS += (((k - 1) >> 1) & 1) ? -gy : gy;
            } else {
                accP += ((k >> 1) & 1) ? -gx : gx;
            }
        }
        float* orow = out + ((size_t)bo * HH + h) * WW;
        orow[64]  = (accP - accS) * sc;
        orow[192] = (accP + accS) * sc;
        orow[128] = acc128 * sc;
    }
}

extern "C" void kernel_launch(void* const* d_in, const int* in_sizes, int n_in,
                              void* d_out, int out_size) {
    const float* x   = (const float*)d_in[0];
    const float* w1r = (const float*)d_in[1];
    const float* w1i = (const float*)d_in[2];
    const float* w2r = (const float*)d_in[3];
    const float* w2i = (const float*)d_in[4];
    float* out = (float*)d_out;

    kAB<<<BB * CC, 256>>>(x);                   // 1024 blocks (fused A+B, double-folded)
    kC<<<QQ * 5, 256>>>(w1r, w1i, w2r, w2i);    // 200 blocks
    kD<<<BB * CC, 256>>>(out);                  // 1024 blocks
}

// round 17
// speedup vs baseline: 1.0555x; 1.0555x over previous
#include <cuda_runtime.h>

// SpectralConv2d via truncated-mode DFTs, fp32 SIMT, register-tiled.
// R16: R15 design with the alignment bug fixed — u/v plane rows padded to
// HH+4 floats (1040B, 16-aligned) so the float4 LDS is legal.

#define BB 16
#define CC 64
#define HH 256
#define WW 256
#define M1 20
#define M2 20
#define QQ 40   // q<20 -> ky=236+q (w2, m=q); q>=20 -> ky=q-20 (w1, m=q-20); freq f = q-20

__device__ float2 g_Zq[BB*CC*QQ*M2];   // after H-DFT   [b,c,q,k2]
__device__ float2 g_Zo[BB*CC*QQ*M2];   // after mixing  [b,o,q,k2]

// ---------------------------------------------------------------------------
// Stage AB (fused): block = one (b,c) slice (grid 1024), 256 threads.
// part 1 (W-DFT): Y[h,k] = sum_w x[h,w] e^{-2pi i k w/256}, folded real input
//   u=x[w]+x[256-w], v=x[w]-x[256-w] (w=1..127), + x0/x128 edge.
//   Planes sfu/sfv[wl][row] (row stride 260 floats = 16B-aligned): warp fetch
//   = 2 contiguous LDS.128.  thread -> (4 rows, 5 k); Y -> smem sY[256][20].
// fold: in place, sY[h] <- Y[h]+Y[h+128], sY[h+128] <- Y[h]-Y[h+128].
// part 2 (H-DFT): Zq[q,k2] = sum_{h<128} plane(f&1)[h][k2] e^{-2pi i f h/256}.
// ---------------------------------------------------------------------------
#define WCH 16
#define HP (HH + 4)   // 260 floats = 1040 bytes per plane row, 16B-aligned
__global__ void __launch_bounds__(256, 2) kAB(const float* __restrict__ x) {
    __shared__ float2 tw[256];             // 2KB
    __shared__ float  sfu[WCH][HP];        // 16.3KB  u plane; [0][r] of chunk0 = x0
    __shared__ float  sfv[WCH][HP];        // 16.3KB  v plane; [0][r] of chunk0 = x128
    __shared__ float2 twa[WCH][M2];        // 2.5KB
    __shared__ float2 sY[HH][M2];          // 40KB
    int tid = threadIdx.x;
    {
        float s, c;
        sincospif((float)tid * (1.0f / 128.0f), &s, &c);
        tw[tid] = make_float2(c, s);
    }
    int bc = blockIdx.x;
    const float* xb = x + (size_t)bc * HH * WW;
    int rg = tid >> 2;             // 0..63 -> rows 4rg..4rg+3
    int k0a = (tid & 3) * 5;

    float ar[4][5], ai[4][5];
    #pragma unroll
    for (int u = 0; u < 4; ++u)
        #pragma unroll
        for (int j = 0; j < 5; ++j) { ar[u][j] = 0.0f; ai[u][j] = 0.0f; }
    float ex[4], e128[4];
    #pragma unroll
    for (int u = 0; u < 4; ++u) { ex[u] = 0.f; e128[u] = 0.f; }

    for (int wc = 0; wc < 128; wc += WCH) {
        __syncthreads();
        // staging: coalesced gmem reads, plane-transposed smem writes
        for (int t = tid; t < HH * WCH; t += 256) {
            int wl = t & (WCH - 1), r = t >> 4;
            int w = wc + wl;
            const float* xr = xb + (size_t)r * WW;
            float a = xr[w];
            if (w == 0) {
                sfu[0][r] = a;          // x0
                sfv[0][r] = xr[128];    // x128
            } else {
                float b = xr[256 - w];
                sfu[wl][r] = a + b;
                sfv[wl][r] = a - b;
            }
        }
        for (int t = tid; t < WCH * M2; t += 256) {
            int wl = t / M2, k = t - wl * M2;
            twa[wl][k] = tw[((wc + wl) * k) & 255];
        }
        __syncthreads();

        int wl0 = 0;
        if (wc == 0) {
            float4 exv = *(const float4*)&sfu[0][4 * rg];
            float4 ev  = *(const float4*)&sfv[0][4 * rg];
            ex[0] = exv.x; ex[1] = exv.y; ex[2] = exv.z; ex[3] = exv.w;
            e128[0] = ev.x; e128[1] = ev.y; e128[2] = ev.z; e128[3] = ev.w;
            wl0 = 1;
        }

        #pragma unroll 2
        for (int wl = wl0; wl < WCH; ++wl) {
            float4 ux = *(const float4*)&sfu[wl][4 * rg];
            float4 vx = *(const float4*)&sfv[wl][4 * rg];
            float ua[4] = {ux.x, ux.y, ux.z, ux.w};
            float va[4] = {vx.x, vx.y, vx.z, vx.w};
            #pragma unroll
            for (int j = 0; j < 5; ++j) {
                float2 cs = twa[wl][k0a + j];
                #pragma unroll
                for (int u = 0; u < 4; ++u) {
                    ar[u][j] = fmaf(ua[u], cs.x, ar[u][j]);
                    ai[u][j] = fmaf(va[u], cs.y, ai[u][j]);
                }
            }
        }
    }

    // Y -> smem
    #pragma unroll
    for (int u = 0; u < 4; ++u) {
        #pragma unroll
        for (int j = 0; j < 5; ++j) {
            int k = k0a + j;
            float re = ar[u][j] + ex[u] + ((k & 1) ? -e128[u] : e128[u]);
            sY[4 * rg + u][k] = make_float2(re, -ai[u][j]);
        }
    }
    __syncthreads();

    // in-place parity fold: sY[h] = Y[h]+Y[h+128], sY[h+128] = Y[h]-Y[h+128]
    for (int t = tid; t < 128 * M2; t += 256) {
        int h = t / M2, k = t - h * M2;
        float2 a = sY[h][k];
        float2 b = sY[h + 128][k];
        sY[h][k]       = make_float2(a.x + b.x, a.y + b.y);
        sY[h + 128][k] = make_float2(a.x - b.x, a.y - b.y);
    }
    __syncthreads();

    // part 2: H-DFT (banked kB loop)
    if (tid < 200) {
        int q = tid / 5;
        int k0 = (tid % 5) * 4;
        int f = q - M1;
        const float2 (*Ys)[M2] = (f & 1) ? (const float2(*)[M2])&sY[128] : (const float2(*)[M2])&sY[0];
        float br[4] = {0, 0, 0, 0}, bi[4] = {0, 0, 0, 0};
        int idx = 0, step = f & 255;
        #pragma unroll 4
        for (int h = 0; h < 128; ++h) {
            float2 cs = tw[idx];
            float4 yab = *(const float4*)&Ys[h][k0];
            float4 ycd = *(const float4*)&Ys[h][k0 + 2];
            float yx[4] = {yab.x, yab.z, ycd.x, ycd.z};
            float yy[4] = {yab.y, yab.w, ycd.y, ycd.w};
            #pragma unroll
            for (int j = 0; j < 4; ++j) {
                br[j] = fmaf(yx[j], cs.x, fmaf(yy[j], cs.y, br[j]));
                bi[j] = fmaf(yy[j], cs.x, fmaf(-yx[j], cs.y, bi[j]));
            }
            idx = (idx + step) & 255;
        }
        float2* zo = g_Zq + (size_t)bc * QQ * M2 + q * M2 + k0;
        #pragma unroll
        for (int j = 0; j < 4; ++j) zo[j] = make_float2(br[j], bi[j]);
    }
}

// ---------------------------------------------------------------------------
// Stage C: Zo[b,o,q,k2] = sum_i Zq[b,i,q,k2] * Wsel[i,o,m,k2]  (complex)
// Block per (q, k2-quad); weights loaded as float4 across 4 k2 (LDG.128);
// thread -> (o, 4 b, 4 k2).
// ---------------------------------------------------------------------------
__global__ void __launch_bounds__(256) kC(const float* __restrict__ w1r, const float* __restrict__ w1i,
                                          const float* __restrict__ w2r, const float* __restrict__ w2i) {
    __shared__ float2 sZ[BB][CC][4];  // 32KB
    int tid = threadIdx.x;
    int q = blockIdx.x / 5, k2b = (blockIdx.x % 5) * 4;

    for (int t = tid; t < BB * CC * 2; t += 256) {
        int pair = t & 1;
        int ci = t >> 1;                 // b*64 + i
        float4 v = *(const float4*)&g_Zq[(size_t)ci * (QQ * M2) + q * M2 + k2b + pair * 2];
        *(float4*)&sZ[ci >> 6][ci & 63][pair * 2] = v;
    }

    const float *wr, *wi;
    int m;
    if (q < M1) { wr = w2r; wi = w2i; m = q; }
    else        { wr = w1r; wi = w1i; m = q - M1; }
    __syncthreads();

    int o = tid & 63;
    int bq = tid >> 6;   // b = bq + 4j
    float ar[4][4], ai[4][4];
    #pragma unroll
    for (int j = 0; j < 4; ++j)
        #pragma unroll
        for (int kk = 0; kk < 4; ++kk) { ar[j][kk] = 0.f; ai[j][kk] = 0.f; }

    size_t wbase = (size_t)o * (M1 * M2) + m * M2 + k2b;
    #pragma unroll 2
    for (int i = 0; i < CC; ++i) {
        float4 wr4 = *(const float4*)&wr[wbase + (size_t)i * (CC * M1 * M2)];
        float4 wi4 = *(const float4*)&wi[wbase + (size_t)i * (CC * M1 * M2)];
        float wra[4] = {wr4.x, wr4.y, wr4.z, wr4.w};
        float wia[4] = {wi4.x, wi4.y, wi4.z, wi4.w};
        #pragma unroll
        for (int j = 0; j < 4; ++j) {
            float4 za = *(const float4*)&sZ[bq + 4 * j][i][0];
            float4 zb = *(const float4*)&sZ[bq + 4 * j][i][2];
            float zx[4] = {za.x, za.z, zb.x, zb.z};
            float zy[4] = {za.y, za.w, zb.y, zb.w};
            #pragma unroll
            for (int kk = 0; kk < 4; ++kk) {
                ar[j][kk] = fmaf(zx[kk], wra[kk], fmaf(-zy[kk], wia[kk], ar[j][kk]));
                ai[j][kk] = fmaf(zx[kk], wia[kk], fmaf( zy[kk], wra[kk], ai[j][kk]));
            }
        }
    }
    #pragma unroll
    for (int j = 0; j < 4; ++j) {
        int b = bq + 4 * j;
        float2* zo = g_Zo + (((size_t)(b * CC + o)) * QQ + q) * M2 + k2b;
        float4 v0 = make_float4(ar[j][0], ai[j][0], ar[j][1], ai[j][1]);
        float4 v1 = make_float4(ar[j][2], ai[j][2], ar[j][3], ai[j][3]);
        *(float4*)&zo[0] = v0;
        *(float4*)&zo[2] = v1;
    }
}

// ---------------------------------------------------------------------------
// Stage D (fused irfft2): block = one bo (grid 1024), 2 CTAs/SM (regs=128).
// phase1: h<->h+128 fold by q-parity. phase2: wp<->128-wp parity fold; one
// twiddle set -> 4 output columns. (Banked R12 form.)
// ---------------------------------------------------------------------------
__global__ void __launch_bounds__(256, 2) kD(float* __restrict__ out) {
    __shared__ float2 tw[256];          // 2KB
    __shared__ float2 sZ[QQ][M2];       // 6.25KB
    __shared__ float  sGx[M2][HH];      // 20KB
    __shared__ float  sGy[M2 - 1][HH];  // 19KB
    __shared__ float  sCw[M2][64];      // 5KB   cos(2pi k wp/256), wp<64
    __shared__ float  sSw[M2][64];      // 5KB   sin(2pi k wp/256), wp<64
    int tid = threadIdx.x;
    {
        float s, c;
        sincospif((float)tid * (1.0f / 128.0f), &s, &c);
        tw[tid] = make_float2(c, s);
    }
    int bo = blockIdx.x;

    const float4* zsrc = (const float4*)(g_Zo + (size_t)bo * QQ * M2);
    float4* zdst = (float4*)&sZ[0][0];
    for (int t = tid; t < QQ * M2 / 2; t += 256) zdst[t] = zsrc[t];
    __syncthreads();

    for (int t = tid; t < M2 * 64; t += 256) {
        int k = t >> 6, wp = t & 63;
        float2 cs = tw[(k * wp) & 255];
        sCw[k][wp] = cs.x;
        sSw[k][wp] = cs.y;
    }

    // ---- phase 1 ----
    {
        int h = tid & 127;
        int k0 = (tid >> 7) * 10;     // 0 or 10
        float ger[10], gei[10], gor[10], goi[10];
        #pragma unroll
        for (int j = 0; j < 10; ++j) { ger[j] = gei[j] = gor[j] = goi[j] = 0.f; }

        int step = (2 * h) & 255;
        int idx = (-20 * h) & 255;
        #pragma unroll 2
        for (int qq = 0; qq < 20; ++qq) {
            float2 cs = tw[idx];
            #pragma unroll
            for (int j = 0; j < 10; ++j) {
                float2 Z = sZ[2 * qq][k0 + j];
                ger[j] = fmaf(Z.x, cs.x, fmaf(-Z.y, cs.y, ger[j]));
                gei[j] = fmaf(Z.x, cs.y, fmaf( Z.y, cs.x, gei[j]));
            }
            idx = (idx + step) & 255;
        }
        idx = (-19 * h) & 255;
        #pragma unroll 2
        for (int qq = 0; qq < 20; ++qq) {
            float2 cs = tw[idx];
            #pragma unroll
            for (int j = 0; j < 10; ++j) {
                float2 Z = sZ[2 * qq + 1][k0 + j];
                gor[j] = fmaf(Z.x, cs.x, fmaf(-Z.y, cs.y, gor[j]));
                goi[j] = fmaf(Z.x, cs.y, fmaf( Z.y, cs.x, goi[j]));
            }
            idx = (idx + step) & 255;
        }
        #pragma unroll
        for (int j = 0; j < 10; ++j) {
            int k = k0 + j;
            sGx[k][h]       = ger[j] + gor[j];
            sGx[k][h + 128] = ger[j] - gor[j];
            if (k > 0) {
                sGy[k - 1][h]       = gei[j] + goi[j];
                sGy[k - 1][h + 128] = gei[j] - goi[j];
            }
        }
    }
    __syncthreads();

    // ---- phase 2: 4h x 2wp tiles, parity-folded over wp ----
    int wpg = tid & 31;       // wp0 = 2*wpg (0..62)
    int hgb = tid >> 5;       // 0..7
    int wp0 = wpg * 2;
    const float sc = 2.0f / 65536.0f;

    #pragma unroll 1
    for (int it = 0; it < 8; ++it) {
        int h0 = it * 32 + hgb * 4;
        float Ce[4][2], Co[4][2], Se[4][2], So[4][2];
        {
            float4 g0 = *(const float4*)&sGx[0][h0];
            float g0a[4] = {g0.x, g0.y, g0.z, g0.w};
            #pragma unroll
            for (int a = 0; a < 4; ++a)
                #pragma unroll
                for (int b = 0; b < 2; ++b) {
                    Ce[a][b] = 0.5f * g0a[a];
                    Co[a][b] = 0.f; Se[a][b] = 0.f; So[a][b] = 0.f;
                }
        }
        #pragma unroll
        for (int k = 1; k < M2; ++k) {
            float4 gx = *(const float4*)&sGx[k][h0];
            float4 gy = *(const float4*)&sGy[k - 1][h0];
            float2 cw = *(const float2*)&sCw[k][wp0];
            float2 sw = *(const float2*)&sSw[k][wp0];
            float gxa[4] = {gx.x, gx.y, gx.z, gx.w};
            float gya[4] = {gy.x, gy.y, gy.z, gy.w};
            float cwb[2] = {cw.x, cw.y};
            float swb[2] = {sw.x, sw.y};
            if (k & 1) {
                #pragma unroll
                for (int a = 0; a < 4; ++a)
                    #pragma unroll
                    for (int b = 0; b < 2; ++b) {
                        Co[a][b] = fmaf(gxa[a], cwb[b], Co[a][b]);
                        So[a][b] = fmaf(gya[a], swb[b], So[a][b]);
                    }
            } else {
                #pragma unroll
                for (int a = 0; a < 4; ++a)
                    #pragma unroll
                    for (int b = 0; b < 2; ++b) {
                        Ce[a][b] = fmaf(gxa[a], cwb[b], Ce[a][b]);
                        Se[a][b] = fmaf(gya[a], swb[b], Se[a][b]);
                    }
            }
        }

        size_t rowbase = ((size_t)bo * HH + h0) * WW;
        #pragma unroll
        for (int a = 0; a < 4; ++a) {
            float* orow = out + rowbase + (size_t)a * WW;
            float o1[2], o2[2], o3[2], o4[2];
            #pragma unroll
            for (int b = 0; b < 2; ++b) {
                float P = Ce[a][b], Q = Co[a][b], R = Se[a][b], T = So[a][b];
                o1[b] = (P + Q - R - T) * sc;   // out[wp]
                o2[b] = (P + Q + R + T) * sc;   // out[256-wp]
                o3[b] = (P - Q + R - T) * sc;   // out[128-wp]
                o4[b] = (P - Q - R + T) * sc;   // out[128+wp]
            }
            *(float2*)&orow[wp0] = make_float2(o1[0], o1[1]);
            if (wpg) {
                orow[256 - wp0]     = o2[0];
                orow[255 - wp0]     = o2[1];
                orow[128 - wp0]     = o3[0];
                orow[127 - wp0]     = o3[1];
                *(float2*)&orow[128 + wp0] = make_float2(o4[0], o4[1]);
            } else {
                orow[255] = o2[1];
                orow[127] = o3[1];
                orow[129] = o4[1];
            }
        }
    }

    // ---- w = 64, 128, 192 columns (per-h epilogue) ----
    {
        int h = tid;
        float g0 = 0.5f * sGx[0][h];
        float accP = g0;
        float accS = 0.f;
        float acc128 = g0;
        #pragma unroll
        for (int k = 1; k < M2; ++k) {
            float gx = sGx[k][h];
            acc128 += (k & 1) ? -gx : gx;
            if (k & 1) {
                float gy = sGy[k - 1][h];
                accS += (((k - 1) >> 1) & 1) ? -gy : gy;
            } else {
                accP += ((k >> 1) & 1) ? -gx : gx;
            }
        }
        float* orow = out + ((size_t)bo * HH + h) * WW;
        orow[64]  = (accP - accS) * sc;
        orow[192] = (accP + accS) * sc;
        orow[128] = acc128 * sc;
    }
}

extern "C" void kernel_launch(void* const* d_in, const int* in_sizes, int n_in,
                              void* d_out, int out_size) {
    const float* x   = (const float*)d_in[0];
    const float* w1r = (const float*)d_in[1];
    const float* w1i = (const float*)d_in[2];
    const float* w2r = (const float*)d_in[3];
    const float* w2i = (const float*)d_in[4];
    float* out = (float*)d_out;

    kAB<<<BB * CC, 256>>>(x);                   // 1024 blocks (fused A+B)
    kC<<<QQ * 5, 256>>>(w1r, w1i, w2r, w2i);    // 200 blocks
    kD<<<BB * CC, 256>>>(out);                  // 1024 blocks
}